// round 5
// baseline (speedup 1.0000x reference)
#include <cuda_runtime.h>
#include <cstdint>

#define BATCH 4096
#define TMAX  2048
#define HID   32

typedef unsigned long long ull;

__device__ int g_perm[BATCH];

// ---------------- fast math helpers ----------------
__device__ __forceinline__ float tanh_fast(float x) {
    float y; asm("tanh.approx.f32 %0, %1;" : "=f"(y) : "f"(x)); return y;
}
// for pre-scaled gate g' = 0.5*(w.h + w_ih x + b): sigmoid = 0.5*tanh(g') + 0.5
__device__ __forceinline__ float sigmoid_prescaled(float g) {
    return fmaf(0.5f, tanh_fast(g), 0.5f);
}
__device__ __forceinline__ float sigmoid_plain(float x) {
    return fmaf(0.5f, tanh_fast(0.5f * x), 0.5f);
}
__device__ __forceinline__ float fast_ex2(float x) {
    float y; asm("ex2.approx.f32 %0, %1;" : "=f"(y) : "f"(x)); return y;
}
__device__ __forceinline__ float expf_fast(float x) {
    return fast_ex2(1.4426950408889634f * x);
}
__device__ __forceinline__ void fma2(ull& d, ull a, ull b) {
    asm("fma.rn.f32x2 %0, %1, %2, %0;" : "+l"(d) : "l"(a), "l"(b));
}
__device__ __forceinline__ float hsum2(ull v) {
    float lo = __uint_as_float((unsigned)(v & 0xffffffffu));
    float hi = __uint_as_float((unsigned)(v >> 32));
    return lo + hi;
}
__device__ __forceinline__ ull pack2(float lo, float hi) {
    return (ull)__float_as_uint(lo) | ((ull)__float_as_uint(hi) << 32);
}

// ---------------- counting sort: longest sequence first ----------------
__global__ void sort_by_len_kernel(const int* __restrict__ lengths) {
    __shared__ int cnt[TMAX];
    __shared__ int tmp[TMAX];
    int tid = threadIdx.x;           // 1024 threads
    for (int i = tid; i < TMAX; i += 1024) cnt[i] = 0;
    __syncthreads();
    for (int i = tid; i < BATCH; i += 1024) {
        int key = TMAX - lengths[i];  // longest first
        atomicAdd(&cnt[key], 1);
    }
    __syncthreads();
    int* src = cnt;
    int* dst = tmp;
    for (int off = 1; off < TMAX; off <<= 1) {
        for (int i = tid; i < TMAX; i += 1024) {
            int v = src[i];
            if (i >= off) v += src[i - off];
            dst[i] = v;
        }
        __syncthreads();
        int* t = src; src = dst; dst = t;
    }
    for (int i = tid; i < TMAX; i += 1024) dst[i] = (i == 0) ? 0 : src[i - 1];
    __syncthreads();
    for (int i = tid; i < BATCH; i += 1024) {
        int key = TMAX - lengths[i];
        int pos = atomicAdd(&dst[key], 1);
        g_perm[pos] = i;
    }
}

// one LSTM step; K = position of x within the current 32-wide chunk
// i,f,o rows pre-scaled by 0.5; g row unscaled.
#define STEP(K) do {                                                        \
    const float xt = __shfl_sync(0xffffffffu, xcur, (K));                   \
    const ull xt2 = pack2(1.0f, xt);                                        \
    ull ai = 0, af = 0, ag = 0, ao = 0;                                     \
    const ulonglong2* hb2 = (const ulonglong2*)sh;                          \
    _Pragma("unroll")                                                       \
    for (int p = 0; p < 8; p++) {                                           \
        const ulonglong2 hv = hb2[p];                                       \
        fma2(ai, wi[2*p], hv.x);  fma2(ai, wi[2*p+1], hv.y);                \
        fma2(af, wf[2*p], hv.x);  fma2(af, wf[2*p+1], hv.y);                \
        fma2(ag, wg[2*p], hv.x);  fma2(ag, wg[2*p+1], hv.y);                \
        fma2(ao, wo[2*p], hv.x);  fma2(ao, wo[2*p+1], hv.y);                \
    }                                                                       \
    fma2(ai, bw_i, xt2);                                                    \
    fma2(af, bw_f, xt2);                                                    \
    fma2(ag, bw_g, xt2);                                                    \
    fma2(ao, bw_o, xt2);                                                    \
    const float I = sigmoid_prescaled(hsum2(ai));                           \
    const float F = sigmoid_prescaled(hsum2(af));                           \
    const float G = tanh_fast(hsum2(ag));                                   \
    const float O = sigmoid_prescaled(hsum2(ao));                           \
    c = fmaf(F, c, I * G);                                                  \
    sh[lane] = O * tanh_fast(c);                                            \
} while (0)

// ---------------- main kernel: one warp (one CTA of 32) per batch element ----------------
__global__ void __launch_bounds__(32, 13) bilstm_kernel(
    const float* __restrict__ x,
    const int*   __restrict__ lengths,
    const float* __restrict__ w_ih,
    const float* __restrict__ w_hh,
    const float* __restrict__ b_ih,
    const float* __restrict__ b_hh,
    const float* __restrict__ fc_w,
    const float* __restrict__ fc_b,
    const float* __restrict__ fc2_w,
    const float* __restrict__ fc2_b,
    float* __restrict__ out)
{
    __shared__ __align__(16) float sh[HID];
    const int lane = threadIdx.x;
    const int b    = g_perm[blockIdx.x];
    const int L    = lengths[b];

    // lane j holds w_hh rows j, j+32, j+64, j+96 (i,f,g,o), packed f32x2.
    // i,f,o rows pre-scaled by 0.5 (sigmoid via tanh identity).
    ull wi[16], wf[16], wg[16], wo[16];
    const float2* W2 = (const float2*)w_hh;
    #pragma unroll
    for (int p = 0; p < 16; p++) {
        float2 a = W2[(lane      ) * 16 + p];
        float2 f = W2[(lane + 32 ) * 16 + p];
        float2 g = W2[(lane + 64 ) * 16 + p];
        float2 o = W2[(lane + 96 ) * 16 + p];
        wi[p] = pack2(0.5f * a.x, 0.5f * a.y);
        wf[p] = pack2(0.5f * f.x, 0.5f * f.y);
        wg[p] = pack2(g.x, g.y);
        wo[p] = pack2(0.5f * o.x, 0.5f * o.y);
    }
    // packed (bias, wih) per gate; multiplied by pack2(1, xt) each step
    const ull bw_i = pack2(0.5f * (b_ih[lane]      + b_hh[lane]),      0.5f * w_ih[lane]);
    const ull bw_f = pack2(0.5f * (b_ih[lane + 32] + b_hh[lane + 32]), 0.5f * w_ih[lane + 32]);
    const ull bw_g = pack2(        b_ih[lane + 64] + b_hh[lane + 64],          w_ih[lane + 64]);
    const ull bw_o = pack2(0.5f * (b_ih[lane + 96] + b_hh[lane + 96]), 0.5f * w_ih[lane + 96]);

    sh[lane] = 0.0f;
    __syncwarp();

    float c = 0.0f;
    const float* xb = x + (size_t)b * TMAX;

    // chunked coalesced x prefetch: one LDG.32 per lane per 32 steps
    int t = L - 1;
    int cbase = t & ~31;
    float xcur  = __ldg(xb + cbase + lane);
    float xnext = (cbase >= 32) ? __ldg(xb + cbase - 32 + lane) : 0.0f;

    // partial (first) chunk: steps t down to cbase, i.e. K = t-cbase .. 0
    for (int k = t - cbase; k >= 0; --k) {
        STEP(k);
    }
    // full chunks of 32, branch-free inner body
    for (cbase -= 32; cbase >= 0; cbase -= 32) {
        xcur  = xnext;
        xnext = (cbase >= 32) ? __ldg(xb + cbase - 32 + lane) : 0.0f;
        #pragma unroll 4
        for (int k = 31; k >= 0; --k) {
            STEP(k);
        }
    }
    __syncwarp();

    // ---------------- MLP head (h replicated through smem) ----------------
    const float* hfin = sh;
    float acc0 = __ldg(fc_b + lane);
    float acc1 = __ldg(fc_b + lane + 32);
    #pragma unroll
    for (int k = 0; k < HID; k++) {
        const float hk = hfin[k];
        acc0 = fmaf(__ldg(fc_w + lane * HID + k),        hk, acc0);
        acc1 = fmaf(__ldg(fc_w + (lane + 32) * HID + k), hk, acc1);
    }
    const float e0 = (acc0 > 0.0f) ? acc0 : (expf_fast(acc0) - 1.0f);
    const float e1 = (acc1 > 0.0f) ? acc1 : (expf_fast(acc1) - 1.0f);
    float p = e0 * __ldg(fc2_w + lane) + e1 * __ldg(fc2_w + lane + 32);
    #pragma unroll
    for (int off = 16; off > 0; off >>= 1)
        p += __shfl_xor_sync(0xffffffffu, p, off);
    if (lane == 0)
        out[b] = sigmoid_plain(p + __ldg(fc2_b));
}

extern "C" void kernel_launch(void* const* d_in, const int* in_sizes, int n_in,
                              void* d_out, int out_size) {
    const float* x     = (const float*)d_in[0];
    const int*   lens  = (const int*)  d_in[1];
    const float* w_ih  = (const float*)d_in[2];
    const float* w_hh  = (const float*)d_in[3];
    const float* b_ih  = (const float*)d_in[4];
    const float* b_hh  = (const float*)d_in[5];
    const float* fc_w  = (const float*)d_in[6];
    const float* fc_b  = (const float*)d_in[7];
    const float* fc2_w = (const float*)d_in[8];
    const float* fc2_b = (const float*)d_in[9];
    float* out = (float*)d_out;

    sort_by_len_kernel<<<1, 1024>>>(lens);
    bilstm_kernel<<<BATCH, 32>>>(x, lens, w_ih, w_hh, b_ih, b_hh,
                                 fc_w, fc_b, fc2_w, fc2_b, out);
}

// round 7
// speedup vs baseline: 1.7431x; 1.7431x over previous
#include <cuda_runtime.h>
#include <cstdint>

#define BATCH 4096
#define TMAX  2048
#define HID   32

typedef unsigned long long ull;

__device__ int g_perm[BATCH];

// ---------------- fast math helpers ----------------
__device__ __forceinline__ float tanh_fast(float x) {
    float y; asm("tanh.approx.f32 %0, %1;" : "=f"(y) : "f"(x)); return y;
}
// gate sums for i/f/o are pre-scaled by 0.5 in the weights: sigmoid = 0.5*tanh(s)+0.5
__device__ __forceinline__ float sigmoid_prescaled(float s) {
    return fmaf(0.5f, tanh_fast(s), 0.5f);
}
__device__ __forceinline__ float sigmoid_plain(float x) {
    return fmaf(0.5f, tanh_fast(0.5f * x), 0.5f);
}
__device__ __forceinline__ float fast_ex2(float x) {
    float y; asm("ex2.approx.f32 %0, %1;" : "=f"(y) : "f"(x)); return y;
}
__device__ __forceinline__ float expf_fast(float x) {
    return fast_ex2(1.4426950408889634f * x);
}
__device__ __forceinline__ void fma2(ull& d, ull a, ull b) {
    asm("fma.rn.f32x2 %0, %1, %2, %0;" : "+l"(d) : "l"(a), "l"(b));
}
__device__ __forceinline__ float hsum2(ull v) {
    float lo = __uint_as_float((unsigned)(v & 0xffffffffu));
    float hi = __uint_as_float((unsigned)(v >> 32));
    return lo + hi;
}
__device__ __forceinline__ ull pack2(float lo, float hi) {
    return (ull)__float_as_uint(lo) | ((ull)__float_as_uint(hi) << 32);
}

// ---------------- counting sort: longest sequence first ----------------
__global__ void sort_by_len_kernel(const int* __restrict__ lengths) {
    __shared__ int cnt[TMAX];
    __shared__ int tmp[TMAX];
    int tid = threadIdx.x;           // 1024 threads
    for (int i = tid; i < TMAX; i += 1024) cnt[i] = 0;
    __syncthreads();
    for (int i = tid; i < BATCH; i += 1024) {
        int key = TMAX - lengths[i];  // longest first
        atomicAdd(&cnt[key], 1);
    }
    __syncthreads();
    int* src = cnt;
    int* dst = tmp;
    for (int off = 1; off < TMAX; off <<= 1) {
        for (int i = tid; i < TMAX; i += 1024) {
            int v = src[i];
            if (i >= off) v += src[i - off];
            dst[i] = v;
        }
        __syncthreads();
        int* t = src; src = dst; dst = t;
    }
    for (int i = tid; i < TMAX; i += 1024) dst[i] = (i == 0) ? 0 : src[i - 1];
    __syncthreads();
    for (int i = tid; i < BATCH; i += 1024) {
        int key = TMAX - lengths[i];
        int pos = atomicAdd(&dst[key], 1);
        g_perm[pos] = i;
    }
}

// one LSTM step; K = position of x within the current 32-wide chunk.
// Each warp computes 2 of the 4 gate sums; raw sums exchanged via double-
// buffered smem; both warps redundantly do the activation + state update
// and keep a private smem copy of h (no second barrier needed).
#define STEP(K) do {                                                        \
    const float xt = __shfl_sync(0xffffffffu, xcur, (K));                   \
    const ull xt2 = pack2(1.0f, xt);                                        \
    ull aa = 0, ab = 0;                                                     \
    const ulonglong2* hb2 = (const ulonglong2*)my_h;                        \
    _Pragma("unroll")                                                       \
    for (int p = 0; p < 8; p++) {                                           \
        const ulonglong2 hv = hb2[p];                                       \
        fma2(aa, wa[2*p], hv.x);  fma2(aa, wa[2*p+1], hv.y);                \
        fma2(ab, wb[2*p], hv.x);  fma2(ab, wb[2*p+1], hv.y);                \
    }                                                                       \
    fma2(aa, bwA, xt2);                                                     \
    fma2(ab, bwB, xt2);                                                     \
    const float2 mine = make_float2(hsum2(aa), hsum2(ab));                  \
    sh_gate[(K) & 1][warp][lane] = mine;                                    \
    __syncthreads();                                                        \
    const float2 og = sh_gate[(K) & 1][1 - warp][lane];                     \
    const float s_i = warp ? og.x   : mine.x;                               \
    const float s_f = warp ? og.y   : mine.y;                               \
    const float s_g = warp ? mine.x : og.x;                                 \
    const float s_o = warp ? mine.y : og.y;                                 \
    const float I = sigmoid_prescaled(s_i);                                 \
    const float F = sigmoid_prescaled(s_f);                                 \
    const float G = tanh_fast(s_g);                                         \
    const float O = sigmoid_prescaled(s_o);                                 \
    c = fmaf(F, c, I * G);                                                  \
    my_h[lane] = O * tanh_fast(c);                                          \
} while (0)

// ---- main kernel: one 64-thread CTA (2 warps) per batch element ----
__global__ void __launch_bounds__(64) bilstm_kernel(
    const float* __restrict__ x,
    const int*   __restrict__ lengths,
    const float* __restrict__ w_ih,
    const float* __restrict__ w_hh,
    const float* __restrict__ b_ih,
    const float* __restrict__ b_hh,
    const float* __restrict__ fc_w,
    const float* __restrict__ fc_b,
    const float* __restrict__ fc2_w,
    const float* __restrict__ fc2_b,
    float* __restrict__ out)
{
    __shared__ __align__(16) float  sh_h[2][HID];        // per-warp private h copy
    __shared__ __align__(16) float2 sh_gate[2][2][HID];  // [parity][warp][unit]
    const int tid  = threadIdx.x;
    const int warp = tid >> 5;
    const int lane = tid & 31;
    const int b    = g_perm[blockIdx.x];
    const int L    = lengths[b];

    // warp0 holds gates i (rows lane) and f (rows lane+32), pre-scaled by 0.5.
    // warp1 holds gates g (rows lane+64, unscaled) and o (rows lane+96, 0.5x).
    const int rowA = lane + warp * 64;
    const int rowB = rowA + 32;
    const float scA = warp ? 1.0f : 0.5f;   // g unscaled, i scaled
    const float scB = 0.5f;                 // f and o both scaled

    ull wa[16], wb[16];
    const float2* W2 = (const float2*)w_hh;
    #pragma unroll
    for (int p = 0; p < 16; p++) {
        float2 a = W2[rowA * 16 + p];
        float2 bq = W2[rowB * 16 + p];
        wa[p] = pack2(scA * a.x,  scA * a.y);
        wb[p] = pack2(scB * bq.x, scB * bq.y);
    }
    const ull bwA = pack2(scA * (b_ih[rowA] + b_hh[rowA]), scA * w_ih[rowA]);
    const ull bwB = pack2(scB * (b_ih[rowB] + b_hh[rowB]), scB * w_ih[rowB]);

    float* my_h = sh_h[warp];
    my_h[lane] = 0.0f;
    // no cross-warp h sharing: each warp reads only its own copy
    __syncwarp();

    float c = 0.0f;
    const float* xb = x + (size_t)b * TMAX;

    // chunked coalesced x prefetch: one LDG.32 per lane per 32 steps (per warp)
    int t = L - 1;
    int cbase = t & ~31;
    float xcur  = __ldg(xb + cbase + lane);
    float xnext = (cbase >= 32) ? __ldg(xb + cbase - 32 + lane) : 0.0f;

    // partial (first) chunk: K = t-cbase .. 0
    for (int k = t - cbase; k >= 0; --k) {
        STEP(k);
    }
    // full chunks of 32, branch-free inner body
    for (cbase -= 32; cbase >= 0; cbase -= 32) {
        xcur  = xnext;
        xnext = (cbase >= 32) ? __ldg(xb + cbase - 32 + lane) : 0.0f;
        #pragma unroll 4
        for (int k = 31; k >= 0; --k) {
            STEP(k);
        }
    }

    // ---------------- MLP head (warp 0 only; reads its own h copy) ----------------
    if (warp == 0) {
        const float* hfin = sh_h[0];
        float acc0 = __ldg(fc_b + lane);
        float acc1 = __ldg(fc_b + lane + 32);
        #pragma unroll
        for (int k = 0; k < HID; k++) {
            const float hk = hfin[k];
            acc0 = fmaf(__ldg(fc_w + lane * HID + k),        hk, acc0);
            acc1 = fmaf(__ldg(fc_w + (lane + 32) * HID + k), hk, acc1);
        }
        const float e0 = (acc0 > 0.0f) ? acc0 : (expf_fast(acc0) - 1.0f);
        const float e1 = (acc1 > 0.0f) ? acc1 : (expf_fast(acc1) - 1.0f);
        float p = e0 * __ldg(fc2_w + lane) + e1 * __ldg(fc2_w + lane + 32);
        #pragma unroll
        for (int off = 16; off > 0; off >>= 1)
            p += __shfl_xor_sync(0xffffffffu, p, off);
        if (lane == 0)
            out[b] = sigmoid_plain(p + __ldg(fc2_b));
    }
}

extern "C" void kernel_launch(void* const* d_in, const int* in_sizes, int n_in,
                              void* d_out, int out_size) {
    const float* x     = (const float*)d_in[0];
    const int*   lens  = (const int*)  d_in[1];
    const float* w_ih  = (const float*)d_in[2];
    const float* w_hh  = (const float*)d_in[3];
    const float* b_ih  = (const float*)d_in[4];
    const float* b_hh  = (const float*)d_in[5];
    const float* fc_w  = (const float*)d_in[6];
    const float* fc_b  = (const float*)d_in[7];
    const float* fc2_w = (const float*)d_in[8];
    const float* fc2_b = (const float*)d_in[9];
    float* out = (float*)d_out;

    sort_by_len_kernel<<<1, 1024>>>(lens);
    bilstm_kernel<<<BATCH, 64>>>(x, lens, w_ih, w_hh, b_ih, b_hh,
                                 fc_w, fc_b, fc2_w, fc2_b, out);
}

// round 9
// speedup vs baseline: 1.8687x; 1.0720x over previous
#include <cuda_runtime.h>
#include <cstdint>

#define BATCH 4096
#define TMAX  2048
#define HID   32

typedef unsigned long long ull;

__device__ int g_perm[BATCH];

// ---------------- fast math helpers ----------------
__device__ __forceinline__ float tanh_fast(float x) {
    float y; asm("tanh.approx.f32 %0, %1;" : "=f"(y) : "f"(x)); return y;
}
// gate sums for i/f/o pre-scaled by 0.5 in weights: sigmoid = 0.5*tanh(s)+0.5
__device__ __forceinline__ float sigmoid_prescaled(float s) {
    return fmaf(0.5f, tanh_fast(s), 0.5f);
}
__device__ __forceinline__ float sigmoid_plain(float x) {
    return fmaf(0.5f, tanh_fast(0.5f * x), 0.5f);
}
__device__ __forceinline__ float fast_ex2(float x) {
    float y; asm("ex2.approx.f32 %0, %1;" : "=f"(y) : "f"(x)); return y;
}
__device__ __forceinline__ float expf_fast(float x) {
    return fast_ex2(1.4426950408889634f * x);
}
__device__ __forceinline__ void fma2(ull& d, ull a, ull b) {
    asm("fma.rn.f32x2 %0, %1, %2, %0;" : "+l"(d) : "l"(a), "l"(b));
}
__device__ __forceinline__ float hsum2(ull v) {
    float lo = __uint_as_float((unsigned)(v & 0xffffffffu));
    float hi = __uint_as_float((unsigned)(v >> 32));
    return lo + hi;
}
__device__ __forceinline__ ull pack2(float lo, float hi) {
    return (ull)__float_as_uint(lo) | ((ull)__float_as_uint(hi) << 32);
}

// ---------------- counting sort: longest sequence first ----------------
__global__ void sort_by_len_kernel(const int* __restrict__ lengths) {
    __shared__ int cnt[TMAX];
    __shared__ int tmp[TMAX];
    int tid = threadIdx.x;           // 1024 threads
    for (int i = tid; i < TMAX; i += 1024) cnt[i] = 0;
    __syncthreads();
    for (int i = tid; i < BATCH; i += 1024) {
        int key = TMAX - lengths[i];  // longest first
        atomicAdd(&cnt[key], 1);
    }
    __syncthreads();
    int* src = cnt;
    int* dst = tmp;
    for (int off = 1; off < TMAX; off <<= 1) {
        for (int i = tid; i < TMAX; i += 1024) {
            int v = src[i];
            if (i >= off) v += src[i - off];
            dst[i] = v;
        }
        __syncthreads();
        int* t = src; src = dst; dst = t;
    }
    for (int i = tid; i < TMAX; i += 1024) dst[i] = (i == 0) ? 0 : src[i - 1];
    __syncthreads();
    for (int i = tid; i < BATCH; i += 1024) {
        int key = TMAX - lengths[i];
        int pos = atomicAdd(&dst[key], 1);
        g_perm[pos] = i;
    }
}

// one LSTM step for TWO independent elements; K = x position in 32-wide chunk.
// elem1's FMA issue block overlaps elem0's activation tail (ILP within warp).
#define STEP2(K) do {                                                       \
    const float xt0 = __shfl_sync(0xffffffffu, xcur0, (K));                 \
    const float xt1 = __shfl_sync(0xffffffffu, xcur1, (K));                 \
    ull ai0 = bi2, af0 = bf2, ag0 = bg2, ao0 = bo2;                         \
    ull ai1 = bi2, af1 = bf2, ag1 = bg2, ao1 = bo2;                         \
    const ulonglong2* hb0 = (const ulonglong2*)sh0;                         \
    const ulonglong2* hb1 = (const ulonglong2*)sh1;                         \
    _Pragma("unroll")                                                       \
    for (int p = 0; p < 8; p++) {                                           \
        const ulonglong2 hv0 = hb0[p];                                      \
        fma2(ai0, wi[2*p], hv0.x);  fma2(ai0, wi[2*p+1], hv0.y);            \
        fma2(af0, wf[2*p], hv0.x);  fma2(af0, wf[2*p+1], hv0.y);            \
        fma2(ag0, wg[2*p], hv0.x);  fma2(ag0, wg[2*p+1], hv0.y);            \
        fma2(ao0, wo[2*p], hv0.x);  fma2(ao0, wo[2*p+1], hv0.y);            \
    }                                                                       \
    _Pragma("unroll")                                                       \
    for (int p = 0; p < 8; p++) {                                           \
        const ulonglong2 hv1 = hb1[p];                                      \
        fma2(ai1, wi[2*p], hv1.x);  fma2(ai1, wi[2*p+1], hv1.y);            \
        fma2(af1, wf[2*p], hv1.x);  fma2(af1, wf[2*p+1], hv1.y);            \
        fma2(ag1, wg[2*p], hv1.x);  fma2(ag1, wg[2*p+1], hv1.y);            \
        fma2(ao1, wo[2*p], hv1.x);  fma2(ao1, wo[2*p+1], hv1.y);            \
    }                                                                       \
    {   /* elem0 tail (always active: t < L0) */                            \
        const float I = sigmoid_prescaled(fmaf(xt0, wih_i, hsum2(ai0)));    \
        const float F = sigmoid_prescaled(fmaf(xt0, wih_f, hsum2(af0)));    \
        const float G = tanh_fast(       fmaf(xt0, wih_g, hsum2(ag0)));     \
        const float O = sigmoid_prescaled(fmaf(xt0, wih_o, hsum2(ao0)));    \
        c0 = fmaf(F, c0, I * G);                                            \
        sh0[lane] = O * tanh_fast(c0);                                      \
    }                                                                       \
    {   /* elem1 tail (masked: active while t < L1) */                      \
        const float I = sigmoid_prescaled(fmaf(xt1, wih_i, hsum2(ai1)));    \
        const float F = sigmoid_prescaled(fmaf(xt1, wih_f, hsum2(af1)));    \
        const float G = tanh_fast(       fmaf(xt1, wih_g, hsum2(ag1)));     \
        const float O = sigmoid_prescaled(fmaf(xt1, wih_o, hsum2(ao1)));    \
        const float cn = fmaf(F, c1, I * G);                                \
        const float hn = O * tanh_fast(cn);                                 \
        const bool act = (cbase + (K)) < L1;                                \
        c1 = act ? cn : c1;                                                 \
        sh1[lane] = act ? hn : sh1[lane];                                   \
    }                                                                       \
} while (0)

// ---- main kernel: one warp (CTA of 32) per TWO batch elements ----
__global__ void __launch_bounds__(32) bilstm_kernel(
    const float* __restrict__ x,
    const int*   __restrict__ lengths,
    const float* __restrict__ w_ih,
    const float* __restrict__ w_hh,
    const float* __restrict__ b_ih,
    const float* __restrict__ b_hh,
    const float* __restrict__ fc_w,
    const float* __restrict__ fc_b,
    const float* __restrict__ fc2_w,
    const float* __restrict__ fc2_b,
    float* __restrict__ out)
{
    __shared__ __align__(16) float sh0[HID];
    __shared__ __align__(16) float sh1[HID];
    const int lane = threadIdx.x;
    const int b0   = g_perm[2 * blockIdx.x];
    const int b1   = g_perm[2 * blockIdx.x + 1];
    const int L0   = lengths[b0];            // sorted desc: L0 >= L1
    const int L1   = lengths[b1];

    // lane j holds w_hh rows j, j+32, j+64, j+96 (i,f,g,o); i/f/o pre-scaled 0.5
    ull wi[16], wf[16], wg[16], wo[16];
    const float2* W2 = (const float2*)w_hh;
    #pragma unroll
    for (int p = 0; p < 16; p++) {
        float2 a = W2[(lane      ) * 16 + p];
        float2 f = W2[(lane + 32 ) * 16 + p];
        float2 g = W2[(lane + 64 ) * 16 + p];
        float2 o = W2[(lane + 96 ) * 16 + p];
        wi[p] = pack2(0.5f * a.x, 0.5f * a.y);
        wf[p] = pack2(0.5f * f.x, 0.5f * f.y);
        wg[p] = pack2(g.x, g.y);
        wo[p] = pack2(0.5f * o.x, 0.5f * o.y);
    }
    const float wih_i = 0.5f * w_ih[lane],      wih_f = 0.5f * w_ih[lane + 32];
    const float wih_g =        w_ih[lane + 64], wih_o = 0.5f * w_ih[lane + 96];
    const ull bi2 = pack2(0.5f * (b_ih[lane]      + b_hh[lane]),      0.0f);
    const ull bf2 = pack2(0.5f * (b_ih[lane + 32] + b_hh[lane + 32]), 0.0f);
    const ull bg2 = pack2(        b_ih[lane + 64] + b_hh[lane + 64],  0.0f);
    const ull bo2 = pack2(0.5f * (b_ih[lane + 96] + b_hh[lane + 96]), 0.0f);

    sh0[lane] = 0.0f;
    sh1[lane] = 0.0f;
    __syncwarp();

    float c0 = 0.0f, c1 = 0.0f;
    const float* xb0 = x + (size_t)b0 * TMAX;
    const float* xb1 = x + (size_t)b1 * TMAX;

    // chunked coalesced x prefetch: one LDG.32 per lane per 32 steps per element
    int t = L0 - 1;
    int cbase = t & ~31;
    float xcur0  = __ldg(xb0 + cbase + lane);
    float xcur1  = __ldg(xb1 + cbase + lane);
    float xnext0 = (cbase >= 32) ? __ldg(xb0 + cbase - 32 + lane) : 0.0f;
    float xnext1 = (cbase >= 32) ? __ldg(xb1 + cbase - 32 + lane) : 0.0f;

    // partial (first) chunk: K = t-cbase .. 0
    for (int k = t - cbase; k >= 0; --k) {
        STEP2(k);
    }
    // full chunks of 32, branch-free inner body
    for (cbase -= 32; cbase >= 0; cbase -= 32) {
        xcur0 = xnext0;
        xcur1 = xnext1;
        const bool more = (cbase >= 32);
        xnext0 = more ? __ldg(xb0 + cbase - 32 + lane) : 0.0f;
        xnext1 = more ? __ldg(xb1 + cbase - 32 + lane) : 0.0f;
        #pragma unroll 2
        for (int k = 31; k >= 0; --k) {
            STEP2(k);
        }
    }
    __syncwarp();

    // ---------------- MLP head for both elements ----------------
    #pragma unroll
    for (int e = 0; e < 2; e++) {
        const float* hfin = e ? sh1 : sh0;
        float acc0 = __ldg(fc_b + lane);
        float acc1 = __ldg(fc_b + lane + 32);
        #pragma unroll
        for (int k = 0; k < HID; k++) {
            const float hk = hfin[k];
            acc0 = fmaf(__ldg(fc_w + lane * HID + k),        hk, acc0);
            acc1 = fmaf(__ldg(fc_w + (lane + 32) * HID + k), hk, acc1);
        }
        const float e0 = (acc0 > 0.0f) ? acc0 : (expf_fast(acc0) - 1.0f);
        const float e1 = (acc1 > 0.0f) ? acc1 : (expf_fast(acc1) - 1.0f);
        float p = e0 * __ldg(fc2_w + lane) + e1 * __ldg(fc2_w + lane + 32);
        #pragma unroll
        for (int off = 16; off > 0; off >>= 1)
            p += __shfl_xor_sync(0xffffffffu, p, off);
        if (lane == 0)
            out[e ? b1 : b0] = sigmoid_plain(p + __ldg(fc2_b));
    }
}

extern "C" void kernel_launch(void* const* d_in, const int* in_sizes, int n_in,
                              void* d_out, int out_size) {
    const float* x     = (const float*)d_in[0];
    const int*   lens  = (const int*)  d_in[1];
    const float* w_ih  = (const float*)d_in[2];
    const float* w_hh  = (const float*)d_in[3];
    const float* b_ih  = (const float*)d_in[4];
    const float* b_hh  = (const float*)d_in[5];
    const float* fc_w  = (const float*)d_in[6];
    const float* fc_b  = (const float*)d_in[7];
    const float* fc2_w = (const float*)d_in[8];
    const float* fc2_b = (const float*)d_in[9];
    float* out = (float*)d_out;

    sort_by_len_kernel<<<1, 1024>>>(lens);
    bilstm_kernel<<<BATCH / 2, 32>>>(x, lens, w_ih, w_hh, b_ih, b_hh,
                                     fc_w, fc_b, fc2_w, fc2_b, out);
}